// round 1
// baseline (speedup 1.0000x reference)
#include <cuda_runtime.h>
#include <cuda_bf16.h>

// KLDivergence: pred_map, true_map are [64, 512, 512] fp32.
// KL_b = D_b/S_t_b + ln(S_p_b/S_t_b), with
//   S_p = sum(p+eps), S_t = sum(t+eps), D = sum((t+eps)*(ln(t+eps)-ln(p+eps)))
// Output = mean over 64 batches. Single HBM pass + tiny finalize.

#define KL_EPS 1e-6f

static constexpr int B        = 64;
static constexpr int N_PER_B  = 512 * 512;        // 262144
static constexpr int V4_PER_B = N_PER_B / 4;      // 65536 float4 per batch
static constexpr int CPB      = 16;               // chunks (blocks) per batch
static constexpr int TPB      = 256;              // threads per block
static constexpr int PER_CHUNK = V4_PER_B / CPB;  // 4096 float4 per chunk

// Deterministic scratch: per-(batch,chunk) partials of (S_p, S_t, D).
__device__ float g_partial[B * CPB * 3];

__device__ __forceinline__ void kl_acc(float p, float t,
                                       float& sp, float& st, float& d) {
    float pp = p + KL_EPS;
    float tt = t + KL_EPS;
    sp += pp;
    st += tt;
    d  += tt * (__logf(tt) - __logf(pp));
}

__global__ __launch_bounds__(TPB)
void kl_stage1(const float4* __restrict__ pred, const float4* __restrict__ tru) {
    const int blk   = blockIdx.x;
    const int batch = blk / CPB;
    const int chunk = blk % CPB;

    const float4* p = pred + (size_t)batch * V4_PER_B + (size_t)chunk * PER_CHUNK;
    const float4* t = tru  + (size_t)batch * V4_PER_B + (size_t)chunk * PER_CHUNK;

    float sp = 0.f, st = 0.f, d = 0.f;

    // 4096 float4 per chunk / 256 threads = 16 iterations; unroll for MLP.
    #pragma unroll 4
    for (int i = threadIdx.x; i < PER_CHUNK; i += TPB) {
        float4 pv = p[i];
        float4 tv = t[i];
        kl_acc(pv.x, tv.x, sp, st, d);
        kl_acc(pv.y, tv.y, sp, st, d);
        kl_acc(pv.z, tv.z, sp, st, d);
        kl_acc(pv.w, tv.w, sp, st, d);
    }

    // Warp reduce (3 values).
    #pragma unroll
    for (int o = 16; o > 0; o >>= 1) {
        sp += __shfl_down_sync(0xFFFFFFFFu, sp, o);
        st += __shfl_down_sync(0xFFFFFFFFu, st, o);
        d  += __shfl_down_sync(0xFFFFFFFFu, d,  o);
    }

    __shared__ float s_sp[TPB / 32];
    __shared__ float s_st[TPB / 32];
    __shared__ float s_d [TPB / 32];
    const int wid = threadIdx.x >> 5;
    const int lid = threadIdx.x & 31;
    if (lid == 0) { s_sp[wid] = sp; s_st[wid] = st; s_d[wid] = d; }
    __syncthreads();

    if (threadIdx.x == 0) {
        float bsp = 0.f, bst = 0.f, bd = 0.f;
        #pragma unroll
        for (int w = 0; w < TPB / 32; w++) { bsp += s_sp[w]; bst += s_st[w]; bd += s_d[w]; }
        g_partial[blk * 3 + 0] = bsp;
        g_partial[blk * 3 + 1] = bst;
        g_partial[blk * 3 + 2] = bd;
    }
}

__global__ __launch_bounds__(B)
void kl_stage2(float* __restrict__ out, int out_size) {
    __shared__ float s_kl[B];
    const int b = threadIdx.x;  // 0..63, one thread per batch

    // Zero the (poisoned) output buffer generically.
    for (int i = b; i < out_size; i += B) out[i] = 0.f;

    float sp = 0.f, st = 0.f, d = 0.f;
    #pragma unroll
    for (int c = 0; c < CPB; c++) {
        const int idx = (b * CPB + c) * 3;
        sp += g_partial[idx + 0];
        st += g_partial[idx + 1];
        d  += g_partial[idx + 2];
    }
    s_kl[b] = d / st + logf(sp / st);
    __syncthreads();

    if (b == 0) {
        float acc = 0.f;
        #pragma unroll
        for (int i = 0; i < B; i++) acc += s_kl[i];
        out[0] = acc * (1.0f / (float)B);
    }
}

extern "C" void kernel_launch(void* const* d_in, const int* in_sizes, int n_in,
                              void* d_out, int out_size) {
    const float4* pred = (const float4*)d_in[0];
    const float4* tru  = (const float4*)d_in[1];
    float* out = (float*)d_out;

    kl_stage1<<<B * CPB, TPB>>>(pred, tru);
    kl_stage2<<<1, B>>>(out, out_size);
}